// round 6
// baseline (speedup 1.0000x reference)
#include <cuda_runtime.h>
#include <cuda_bf16.h>
#include <cstdint>

#define H_DIM 65536
#define DIMC 384
#define KPAD 896   // 882 padded to 14*64

// ---------------- device scratch (allowed: __device__ globals) ----------------
__device__ __align__(16) __nv_bfloat16 g_cbf[(size_t)H_DIM * KPAD];   // corr, bf16, [h][k]
__device__ __align__(16) __nv_bfloat16 g_bufA[(size_t)H_DIM * DIMC];
__device__ __align__(16) __nv_bfloat16 g_bufB[(size_t)H_DIM * DIMC];
__device__ __align__(16) __nv_bfloat16 g_bufC[(size_t)H_DIM * DIMC];  // bf16 copy of x4
__device__ __align__(16) float         g_xf  [(size_t)H_DIM * DIMC];  // fp32 residual master
__device__ __align__(16) __nv_bfloat16 g_w1 [(size_t)DIMC * KPAD];    // cc_w1 padded
__device__ __align__(16) __nv_bfloat16 g_w2 [DIMC * DIMC];
__device__ __align__(16) __nv_bfloat16 g_w3 [DIMC * DIMC];
__device__ __align__(16) __nv_bfloat16 g_c11[DIMC * DIMC];
__device__ __align__(16) __nv_bfloat16 g_c12[DIMC * DIMC];
__device__ __align__(16) __nv_bfloat16 g_c21[DIMC * DIMC];
__device__ __align__(16) __nv_bfloat16 g_c22[DIMC * DIMC];

// ---------------- low-level helpers (baseline sm_80+ ISA only) ----------------
__device__ __forceinline__ uint32_t smem_u32(const void* p) {
    uint32_t a;
    asm("{ .reg .u64 t; cvta.to.shared.u64 t, %1; cvt.u32.u64 %0, t; }" : "=r"(a) : "l"(p));
    return a;
}
__device__ __forceinline__ void cpasync16(uint32_t s, const void* g) {
    asm volatile("cp.async.cg.shared.global [%0], [%1], 16;" :: "r"(s), "l"(g));
}
#define CP_COMMIT() asm volatile("cp.async.commit_group;" ::: "memory")
#define CP_WAIT(n)  asm volatile("cp.async.wait_group %0;" :: "n"(n) : "memory")

__device__ __forceinline__ void ldsm_x4(uint32_t* r, uint32_t a) {
    asm volatile("ldmatrix.sync.aligned.m8n8.x4.shared.b16 {%0,%1,%2,%3}, [%4];"
                 : "=r"(r[0]), "=r"(r[1]), "=r"(r[2]), "=r"(r[3]) : "r"(a));
}
__device__ __forceinline__ void ldsm_x2(uint32_t* r, uint32_t a) {
    asm volatile("ldmatrix.sync.aligned.m8n8.x2.shared.b16 {%0,%1}, [%2];"
                 : "=r"(r[0]), "=r"(r[1]) : "r"(a));
}
__device__ __forceinline__ void mma16816(float* c, const uint32_t* a, const uint32_t* b) {
    asm volatile("mma.sync.aligned.m16n8k16.row.col.f32.bf16.bf16.f32 "
                 "{%0,%1,%2,%3}, {%4,%5,%6,%7}, {%8,%9}, {%0,%1,%2,%3};"
                 : "+f"(c[0]), "+f"(c[1]), "+f"(c[2]), "+f"(c[3])
                 : "r"(a[0]), "r"(a[1]), "r"(a[2]), "r"(a[3]), "r"(b[0]), "r"(b[1]));
}

// ---------------- prologue kernels ----------------
__global__ void conv_w_kernel(const float* __restrict__ src, __nv_bfloat16* __restrict__ dst,
                              int ksrc, int kdst, int total) {
    int i = blockIdx.x * blockDim.x + threadIdx.x;
    if (i >= total) return;
    int n = i / kdst, k = i - n * kdst;
    dst[i] = (k < ksrc) ? __float2bfloat16(src[n * ksrc + k]) : __float2bfloat16(0.0f);
}

// corr [1,882,H,1] -> bf16 [h][k] padded to KPAD (transpose+convert), 128x64 tiles
__global__ void corr_prep_kernel(const float* __restrict__ corr, __nv_bfloat16* __restrict__ dst) {
    __shared__ __nv_bfloat16 t[128 * 80];
    int h0 = blockIdx.x * 128, k0 = blockIdx.y * 64;
    int tid = threadIdx.x;
    for (int i = tid; i < 128 * 64; i += 256) {
        int k = i >> 7, h = i & 127;
        int gk = k0 + k;
        float v = (gk < 882) ? corr[(size_t)gk * H_DIM + h0 + h] : 0.0f;
        t[h * 80 + k] = __float2bfloat16(v);
    }
    __syncthreads();
    for (int i = tid; i < 128 * 8; i += 256) {
        int h = i >> 3, kq = i & 7;
        uint4 v = *(const uint4*)(&t[h * 80 + kq * 8]);
        *(uint4*)(dst + (size_t)(h0 + h) * KPAD + k0 + kq * 8) = v;
    }
}

// ---------------- GEMM: out[h][n] = sum_k A[h][k]*W[n][k] + bias[n] ----------------
// MODE 0: relu -> out_bf ; MODE 1: store fp32 -> out_f ; MODE 2: out_f += v
#define ROWP 72                       // padded smem row stride (elements)
#define TILE_ELEMS (128 * ROWP)       // 9216 elems = 18432 B
#define SMEM_BYTES (4 * TILE_ELEMS * 2)

template <int MODE>
__global__ void __launch_bounds__(256)
gemm_kernel(const __nv_bfloat16* __restrict__ A, int lda, int K,
            const __nv_bfloat16* __restrict__ W, int ldb,
            const float* __restrict__ bias,
            __nv_bfloat16* __restrict__ out_bf,
            float* __restrict__ out_f) {
    extern __shared__ __align__(16) __nv_bfloat16 smem[];
    // layout: A0, A1, B0, B1 (each TILE_ELEMS)
    const int tid = threadIdx.x, wid = tid >> 5, lane = tid & 31;
    const int n0 = blockIdx.x * 128, h0 = blockIdx.y * 128;
    const int wm = wid & 1, wn = wid >> 1;   // warp tile: 64(M) x 32(N)

    uint32_t sbase = smem_u32(smem);
    const uint32_t sA[2] = { sbase, sbase + TILE_ELEMS * 2 };
    const uint32_t sB[2] = { sbase + 2 * TILE_ELEMS * 2, sbase + 3 * TILE_ELEMS * 2 };

    float acc[4][4][4];
#pragma unroll
    for (int i = 0; i < 4; i++)
#pragma unroll
        for (int j = 0; j < 4; j++)
#pragma unroll
            for (int r = 0; r < 4; r++) acc[i][j][r] = 0.0f;

    // per-thread ldmatrix base offsets (bytes)
    const uint32_t aOff = ((uint32_t)(wm * 64 + (lane & 15)) * ROWP + (uint32_t)(lane >> 4) * 8) * 2;
    const int Lb = lane & 15;
    const uint32_t bOff = ((uint32_t)(wn * 32 + (Lb & 7)) * ROWP + (uint32_t)(Lb >> 3) * 8) * 2;

    const int nk = K >> 6;

    // chunk loader: 2048 x 16B (A: 1024, B: 1024)
    auto issue = [&](int kc, int buf) {
#pragma unroll
        for (int it = 0; it < 8; it++) {
            int i = tid + it * 256;
            int half = i >> 10, j = i & 1023, row = j >> 3, q = j & 7;
            uint32_t soff = (uint32_t)(row * ROWP + q * 8) * 2;
            if (half == 0)
                cpasync16(sA[buf] + soff, A + (size_t)(h0 + row) * lda + kc * 64 + q * 8);
            else
                cpasync16(sB[buf] + soff, W + (size_t)(n0 + row) * ldb + kc * 64 + q * 8);
        }
        CP_COMMIT();
    };

    issue(0, 0);
    int buf = 0;
    for (int kc = 0; kc < nk; kc++) {
        if (kc + 1 < nk) {
            issue(kc + 1, buf ^ 1);
            CP_WAIT(1);
        } else {
            CP_WAIT(0);
        }
        __syncthreads();
#pragma unroll
        for (int ks = 0; ks < 4; ks++) {
            uint32_t af[4][4], bfr[4][2];
#pragma unroll
            for (int m = 0; m < 4; m++)
                ldsm_x4(af[m], sA[buf] + aOff + (uint32_t)(m * 16 * ROWP + ks * 16) * 2);
#pragma unroll
            for (int n = 0; n < 4; n++)
                ldsm_x2(bfr[n], sB[buf] + bOff + (uint32_t)(n * 8 * ROWP + ks * 16) * 2);
#pragma unroll
            for (int m = 0; m < 4; m++)
#pragma unroll
                for (int n = 0; n < 4; n++)
                    mma16816(acc[m][n], af[m], bfr[n]);
        }
        __syncthreads();
        buf ^= 1;
    }

    // epilogue
    const int rbase = h0 + wm * 64 + (lane >> 2);
    const int cbase = n0 + wn * 32 + 2 * (lane & 3);
#pragma unroll
    for (int m = 0; m < 4; m++) {
#pragma unroll
        for (int n = 0; n < 4; n++) {
            int col = cbase + n * 8;
            float bia0 = bias[col], bia1 = bias[col + 1];
#pragma unroll
            for (int half = 0; half < 2; half++) {
                int row = rbase + m * 16 + half * 8;
                float v0 = acc[m][n][half * 2 + 0] + bia0;
                float v1 = acc[m][n][half * 2 + 1] + bia1;
                if (MODE == 0) {
                    v0 = fmaxf(v0, 0.0f); v1 = fmaxf(v1, 0.0f);
                    *(__nv_bfloat162*)(out_bf + (size_t)row * DIMC + col) =
                        __floats2bfloat162_rn(v0, v1);
                } else if (MODE == 1) {
                    float* p = out_f + (size_t)row * DIMC + col;
                    p[0] = v0; p[1] = v1;
                } else {
                    float* p = out_f + (size_t)row * DIMC + col;
                    p[0] += v0; p[1] += v1;
                }
            }
        }
    }
}

// ---------------- xf += net + inp (transposed gather) ; also emit bf16 copy ----------------
__global__ void add_ni_kernel(const float* __restrict__ net, const float* __restrict__ inp,
                              float* __restrict__ xf, __nv_bfloat16* __restrict__ xbf) {
    __shared__ float t[128 * 33];
    int h0 = blockIdx.x * 128, c0 = blockIdx.y * 32;
    int tid = threadIdx.x;
    for (int i = tid; i < 32 * 128; i += 256) {
        int c = i >> 7, h = i & 127;
        size_t g = (size_t)(c0 + c) * H_DIM + h0 + h;
        t[h * 33 + c] = net[g] + inp[g];
    }
    __syncthreads();
    for (int i = tid; i < 128 * 32; i += 256) {
        int h = i >> 5, c = i & 31;
        size_t g = (size_t)(h0 + h) * DIMC + c0 + c;
        float v = xf[g] + t[h * 33 + c];
        xf[g] = v;
        xbf[g] = __float2bfloat16(v);
    }
}

// ---------------- final transpose: xf [h][c] -> out [c][H] ----------------
__global__ void transpose_kernel(const float* __restrict__ xf, float* __restrict__ out) {
    __shared__ float t[128 * 33];
    int h0 = blockIdx.x * 128, c0 = blockIdx.y * 32;
    int tid = threadIdx.x;
    for (int i = tid; i < 128 * 32; i += 256) {
        int h = i >> 5, c = i & 31;
        t[h * 33 + c] = xf[(size_t)(h0 + h) * DIMC + c0 + c];
    }
    __syncthreads();
    for (int i = tid; i < 128 * 32; i += 256) {
        int c = i >> 7, h = i & 127;
        out[(size_t)(c0 + c) * H_DIM + h0 + h] = t[h * 33 + c];
    }
}

// ---------------- heads: warp per row ----------------
__global__ void heads_kernel(const float* __restrict__ xf,
                             const float* __restrict__ dw, const float* __restrict__ db,
                             const float* __restrict__ ww, const float* __restrict__ wb,
                             float* __restrict__ out) {
    int g = blockIdx.x * blockDim.x + threadIdx.x;
    int warp = g >> 5, lane = g & 31;
    if (warp >= H_DIM) return;
    const float* xr = xf + (size_t)warp * DIMC;
    float d0 = 0, d1 = 0, w0 = 0, w1 = 0;
#pragma unroll
    for (int i = 0; i < 12; i++) {
        int c = lane + 32 * i;
        float r = fmaxf(xr[c], 0.0f);
        d0 += r * dw[c];  d1 += r * dw[DIMC + c];
        w0 += r * ww[c];  w1 += r * ww[DIMC + c];
    }
#pragma unroll
    for (int off = 16; off; off >>= 1) {
        d0 += __shfl_xor_sync(0xFFFFFFFFu, d0, off);
        d1 += __shfl_xor_sync(0xFFFFFFFFu, d1, off);
        w0 += __shfl_xor_sync(0xFFFFFFFFu, w0, off);
        w1 += __shfl_xor_sync(0xFFFFFFFFu, w1, off);
    }
    if (lane == 0) {
        size_t base = (size_t)DIMC * H_DIM;
        out[base + 0 * H_DIM + warp] = d0 + db[0];
        out[base + 1 * H_DIM + warp] = d1 + db[1];
        out[base + 2 * H_DIM + warp] = 1.0f / (1.0f + expf(-(w0 + wb[0])));
        out[base + 3 * H_DIM + warp] = 1.0f / (1.0f + expf(-(w1 + wb[1])));
    }
}

// ---------------- launch ----------------
extern "C" void kernel_launch(void* const* d_in, const int* in_sizes, int n_in,
                              void* d_out, int out_size) {
    const float* net   = (const float*)d_in[0];
    const float* inp   = (const float*)d_in[1];
    const float* corr  = (const float*)d_in[2];
    const float* cc_w1 = (const float*)d_in[7];
    const float* cc_b1 = (const float*)d_in[8];
    const float* cc_w2 = (const float*)d_in[9];
    const float* cc_b2 = (const float*)d_in[10];
    const float* cc_w3 = (const float*)d_in[11];
    const float* cc_b3 = (const float*)d_in[12];
    const float* c1_w1 = (const float*)d_in[13];
    const float* c1_b1 = (const float*)d_in[14];
    const float* c1_w2 = (const float*)d_in[15];
    const float* c1_b2 = (const float*)d_in[16];
    const float* c2_w1 = (const float*)d_in[17];
    const float* c2_b1 = (const float*)d_in[18];
    const float* c2_w2 = (const float*)d_in[19];
    const float* c2_b2 = (const float*)d_in[20];
    const float* dW    = (const float*)d_in[21];
    const float* dB    = (const float*)d_in[22];
    const float* wW    = (const float*)d_in[23];
    const float* wB    = (const float*)d_in[24];
    float* out = (float*)d_out;

    void *p_cbf, *p_a, *p_b, *p_c, *p_xf;
    void *p_w1, *p_w2, *p_w3, *p_c11, *p_c12, *p_c21, *p_c22;
    cudaGetSymbolAddress(&p_cbf, g_cbf);
    cudaGetSymbolAddress(&p_a, g_bufA);
    cudaGetSymbolAddress(&p_b, g_bufB);
    cudaGetSymbolAddress(&p_c, g_bufC);
    cudaGetSymbolAddress(&p_xf, g_xf);
    cudaGetSymbolAddress(&p_w1, g_w1);
    cudaGetSymbolAddress(&p_w2, g_w2);
    cudaGetSymbolAddress(&p_w3, g_w3);
    cudaGetSymbolAddress(&p_c11, g_c11);
    cudaGetSymbolAddress(&p_c12, g_c12);
    cudaGetSymbolAddress(&p_c21, g_c21);
    cudaGetSymbolAddress(&p_c22, g_c22);

    cudaFuncSetAttribute(gemm_kernel<0>, cudaFuncAttributeMaxDynamicSharedMemorySize, SMEM_BYTES);
    cudaFuncSetAttribute(gemm_kernel<1>, cudaFuncAttributeMaxDynamicSharedMemorySize, SMEM_BYTES);
    cudaFuncSetAttribute(gemm_kernel<2>, cudaFuncAttributeMaxDynamicSharedMemorySize, SMEM_BYTES);

    typedef __nv_bfloat16 bf;
    // weight conversion (fp32 -> bf16, K-padded where needed)
    conv_w_kernel<<<(DIMC * KPAD + 255) / 256, 256>>>(cc_w1, (bf*)p_w1, 882, KPAD, DIMC * KPAD);
    conv_w_kernel<<<576, 256>>>(cc_w2, (bf*)p_w2, DIMC, DIMC, DIMC * DIMC);
    conv_w_kernel<<<576, 256>>>(cc_w3, (bf*)p_w3, DIMC, DIMC, DIMC * DIMC);
    conv_w_kernel<<<576, 256>>>(c1_w1, (bf*)p_c11, DIMC, DIMC, DIMC * DIMC);
    conv_w_kernel<<<576, 256>>>(c1_w2, (bf*)p_c12, DIMC, DIMC, DIMC * DIMC);
    conv_w_kernel<<<576, 256>>>(c2_w1, (bf*)p_c21, DIMC, DIMC, DIMC * DIMC);
    conv_w_kernel<<<576, 256>>>(c2_w2, (bf*)p_c22, DIMC, DIMC, DIMC * DIMC);
    // corr transpose + convert
    corr_prep_kernel<<<dim3(H_DIM / 128, KPAD / 64), 256>>>(corr, (bf*)p_cbf);

    dim3 gg(DIMC / 128, H_DIM / 128);
    // t1 = relu(W1 @ corr + b1)
    gemm_kernel<0><<<gg, 256, SMEM_BYTES>>>((bf*)p_cbf, KPAD, KPAD, (bf*)p_w1, KPAD,
                                            cc_b1, (bf*)p_a, nullptr);
    // t2 = relu(W2 @ t1 + b2)
    gemm_kernel<0><<<gg, 256, SMEM_BYTES>>>((bf*)p_a, DIMC, DIMC, (bf*)p_w2, DIMC,
                                            cc_b2, (bf*)p_b, nullptr);
    // xf = W3 @ t2 + b3  (fp32)
    gemm_kernel<1><<<gg, 256, SMEM_BYTES>>>((bf*)p_b, DIMC, DIMC, (bf*)p_w3, DIMC,
                                            cc_b3, nullptr, (float*)p_xf);
    // xf += net + inp ; bufC = bf16(xf)   (this is x4)
    add_ni_kernel<<<dim3(H_DIM / 128, DIMC / 32), 256>>>(net, inp, (float*)p_xf, (bf*)p_c);
    // h1 = relu(c1w1 @ x4 + b)
    gemm_kernel<0><<<gg, 256, SMEM_BYTES>>>((bf*)p_c, DIMC, DIMC, (bf*)p_c11, DIMC,
                                            c1_b1, (bf*)p_a, nullptr);
    // xf += c1w2 @ h1 + b
    gemm_kernel<2><<<gg, 256, SMEM_BYTES>>>((bf*)p_a, DIMC, DIMC, (bf*)p_c12, DIMC,
                                            c1_b2, nullptr, (float*)p_xf);
    // h2 = relu(c2w1 @ x4 + b)
    gemm_kernel<0><<<gg, 256, SMEM_BYTES>>>((bf*)p_c, DIMC, DIMC, (bf*)p_c21, DIMC,
                                            c2_b1, (bf*)p_b, nullptr);
    // xf += c2w2 @ h2 + b
    gemm_kernel<2><<<gg, 256, SMEM_BYTES>>>((bf*)p_b, DIMC, DIMC, (bf*)p_c22, DIMC,
                                            c2_b2, nullptr, (float*)p_xf);

    // net_out (transposed) + heads
    transpose_kernel<<<dim3(H_DIM / 128, DIMC / 32), 256>>>((float*)p_xf, out);
    heads_kernel<<<(H_DIM * 32) / 256, 256>>>((float*)p_xf, dW, dB, wW, wB, out);
}

// round 8
// speedup vs baseline: 1.3272x; 1.3272x over previous
#include <cuda_runtime.h>
#include <cuda_bf16.h>
#include <cstdint>

#define H_DIM 65536
#define DIMC 384
#define KPAD 896   // 882 padded to 14*64

// ---------------- device scratch (allowed: __device__ globals) ----------------
__device__ __align__(16) __nv_bfloat16 g_cbf[(size_t)H_DIM * KPAD];   // corr, bf16, [h][k]
__device__ __align__(16) __nv_bfloat16 g_bufA[(size_t)H_DIM * DIMC];
__device__ __align__(16) __nv_bfloat16 g_bufB[(size_t)H_DIM * DIMC];
__device__ __align__(16) __nv_bfloat16 g_bufC[(size_t)H_DIM * DIMC];  // bf16 copy of x4
__device__ __align__(16) __nv_bfloat16 g_bufH[(size_t)H_DIM * 768];   // [h1|h2]
__device__ __align__(16) float         g_xf  [(size_t)H_DIM * DIMC];  // fp32 residual master
__device__ __align__(16) __nv_bfloat16 g_w1 [(size_t)DIMC * KPAD];    // cc_w1 padded
__device__ __align__(16) __nv_bfloat16 g_w2 [DIMC * DIMC];
__device__ __align__(16) __nv_bfloat16 g_w3 [DIMC * DIMC];
__device__ __align__(16) __nv_bfloat16 g_w45[768 * DIMC];             // [c1w1 ; c2w1]
__device__ __align__(16) __nv_bfloat16 g_w67[DIMC * 768];             // [c1w2 | c2w2] along K
__device__ __align__(16) float         g_b45[768];
__device__ __align__(16) float         g_b67[DIMC];

// ---------------- low-level helpers (baseline sm_80+ ISA only) ----------------
__device__ __forceinline__ uint32_t smem_u32(const void* p) {
    uint32_t a;
    asm("{ .reg .u64 t; cvta.to.shared.u64 t, %1; cvt.u32.u64 %0, t; }" : "=r"(a) : "l"(p));
    return a;
}
__device__ __forceinline__ void cpasync16(uint32_t s, const void* g) {
    asm volatile("cp.async.cg.shared.global [%0], [%1], 16;" :: "r"(s), "l"(g));
}
#define CP_COMMIT() asm volatile("cp.async.commit_group;" ::: "memory")
#define CP_WAIT(n)  asm volatile("cp.async.wait_group %0;" :: "n"(n) : "memory")

__device__ __forceinline__ void ldsm_x4(uint32_t* r, uint32_t a) {
    asm volatile("ldmatrix.sync.aligned.m8n8.x4.shared.b16 {%0,%1,%2,%3}, [%4];"
                 : "=r"(r[0]), "=r"(r[1]), "=r"(r[2]), "=r"(r[3]) : "r"(a));
}
__device__ __forceinline__ void ldsm_x2(uint32_t* r, uint32_t a) {
    asm volatile("ldmatrix.sync.aligned.m8n8.x2.shared.b16 {%0,%1}, [%2];"
                 : "=r"(r[0]), "=r"(r[1]) : "r"(a));
}
__device__ __forceinline__ void mma16816(float* c, const uint32_t* a, const uint32_t* b) {
    asm volatile("mma.sync.aligned.m16n8k16.row.col.f32.bf16.bf16.f32 "
                 "{%0,%1,%2,%3}, {%4,%5,%6,%7}, {%8,%9}, {%0,%1,%2,%3};"
                 : "+f"(c[0]), "+f"(c[1]), "+f"(c[2]), "+f"(c[3])
                 : "r"(a[0]), "r"(a[1]), "r"(a[2]), "r"(a[3]), "r"(b[0]), "r"(b[1]));
}

// ---------------- prologue: all weight prep in one region-dispatched kernel ----------------
// regions (blocks of 256 thr):
//  [0,1344)    w1 pad 882->896
//  [1344,1920) w2
//  [1920,2496) w3
//  [2496,3648) w45 = [c1w1 ; c2w1]     (768 x 384)
//  [3648,4800) w67 = [c1w2 | c2w2]     (384 x 768, concat along K)
//  [4800,4803) b45 = [c1b1 ; c2b1]
//  [4803,4805) b67 = c1b2 + c2b2
__global__ void prep_kernel(const float* __restrict__ cc_w1,
                            const float* __restrict__ cc_w2,
                            const float* __restrict__ cc_w3,
                            const float* __restrict__ c1w1, const float* __restrict__ c1b1,
                            const float* __restrict__ c1w2, const float* __restrict__ c1b2,
                            const float* __restrict__ c2w1, const float* __restrict__ c2b1,
                            const float* __restrict__ c2w2, const float* __restrict__ c2b2,
                            __nv_bfloat16* __restrict__ w1, __nv_bfloat16* __restrict__ w2,
                            __nv_bfloat16* __restrict__ w3, __nv_bfloat16* __restrict__ w45,
                            __nv_bfloat16* __restrict__ w67,
                            float* __restrict__ b45, float* __restrict__ b67) {
    int b = blockIdx.x, t = threadIdx.x;
    if (b < 1344) {
        int i = b * 256 + t;
        if (i < DIMC * KPAD) {
            int n = i / KPAD, k = i - n * KPAD;
            w1[i] = (k < 882) ? __float2bfloat16(cc_w1[n * 882 + k]) : __float2bfloat16(0.0f);
        }
    } else if (b < 1920) {
        int i = (b - 1344) * 256 + t;
        w2[i] = __float2bfloat16(cc_w2[i]);
    } else if (b < 2496) {
        int i = (b - 1920) * 256 + t;
        w3[i] = __float2bfloat16(cc_w3[i]);
    } else if (b < 3648) {
        int i = (b - 2496) * 256 + t;       // 768*384
        int n = i / DIMC, k = i - n * DIMC;
        float v = (n < DIMC) ? c1w1[n * DIMC + k] : c2w1[(n - DIMC) * DIMC + k];
        w45[i] = __float2bfloat16(v);
    } else if (b < 4800) {
        int i = (b - 3648) * 256 + t;       // 384*768
        int n = i / 768, k = i - n * 768;
        float v = (k < DIMC) ? c1w2[n * DIMC + k] : c2w2[n * DIMC + (k - DIMC)];
        w67[i] = __float2bfloat16(v);
    } else if (b < 4803) {
        int i = (b - 4800) * 256 + t;
        if (i < 768) b45[i] = (i < DIMC) ? c1b1[i] : c2b1[i - DIMC];
    } else {
        int i = (b - 4803) * 256 + t;
        if (i < DIMC) b67[i] = c1b2[i] + c2b2[i];
    }
}

// corr [1,882,H,1] -> bf16 [h][k] padded to KPAD (transpose+convert), 128x64 tiles
__global__ void corr_prep_kernel(const float* __restrict__ corr, __nv_bfloat16* __restrict__ dst) {
    __shared__ __nv_bfloat16 t[128 * 80];
    int h0 = blockIdx.x * 128, k0 = blockIdx.y * 64;
    int tid = threadIdx.x;
    for (int i = tid; i < 128 * 64; i += 256) {
        int k = i >> 7, h = i & 127;
        int gk = k0 + k;
        float v = (gk < 882) ? corr[(size_t)gk * H_DIM + h0 + h] : 0.0f;
        t[h * 80 + k] = __float2bfloat16(v);
    }
    __syncthreads();
    for (int i = tid; i < 128 * 8; i += 256) {
        int h = i >> 3, kq = i & 7;
        uint4 v = *(const uint4*)(&t[h * 80 + kq * 8]);
        *(uint4*)(dst + (size_t)(h0 + h) * KPAD + k0 + kq * 8) = v;
    }
}

// ---------------- GEMM: tile 128(M) x 128(N), 8 warps, K chunked by 64 ----------------
// MODE 0: relu -> out_bf (stride ldo)
// MODE 1: v += net+inp (transposed gather); xf = v (fp32); out_bf = bf16(v)   [x4]
// MODE 2: v += xf; outT[col*H + row] = v                                      [final]
#define ROWP 72
#define TILE_ELEMS (128 * ROWP)
#define SMEM_BYTES (4 * TILE_ELEMS * 2)

template <int MODE>
__global__ void __launch_bounds__(256)
gemm_kernel(const __nv_bfloat16* __restrict__ A, int lda, int K,
            const __nv_bfloat16* __restrict__ W, int ldb,
            const float* __restrict__ bias,
            __nv_bfloat16* __restrict__ out_bf, int ldo,
            float* __restrict__ xf,
            const float* __restrict__ net, const float* __restrict__ inp,
            float* __restrict__ outT) {
    extern __shared__ __align__(16) __nv_bfloat16 smem[];
    const int tid = threadIdx.x, wid = tid >> 5, lane = tid & 31;
    const int n0 = blockIdx.x * 128, h0 = blockIdx.y * 128;
    const int wm = wid & 1, wn = wid >> 1;   // warp tile: 64(M) x 32(N)

    uint32_t sbase = smem_u32(smem);
    const uint32_t sA[2] = { sbase, sbase + TILE_ELEMS * 2 };
    const uint32_t sB[2] = { sbase + 2 * TILE_ELEMS * 2, sbase + 3 * TILE_ELEMS * 2 };

    float acc[4][4][4];
#pragma unroll
    for (int i = 0; i < 4; i++)
#pragma unroll
        for (int j = 0; j < 4; j++)
#pragma unroll
            for (int r = 0; r < 4; r++) acc[i][j][r] = 0.0f;

    const uint32_t aOff = ((uint32_t)(wm * 64 + (lane & 15)) * ROWP + (uint32_t)(lane >> 4) * 8) * 2;
    const int Lb = lane & 15;
    const uint32_t bOff = ((uint32_t)(wn * 32 + (Lb & 7)) * ROWP + (uint32_t)(Lb >> 3) * 8) * 2;

    const int nk = K >> 6;

    auto issue = [&](int kc, int buf) {
#pragma unroll
        for (int it = 0; it < 8; it++) {
            int i = tid + it * 256;
            int half = i >> 10, j = i & 1023, row = j >> 3, q = j & 7;
            uint32_t soff = (uint32_t)(row * ROWP + q * 8) * 2;
            if (half == 0)
                cpasync16(sA[buf] + soff, A + (size_t)(h0 + row) * lda + kc * 64 + q * 8);
            else
                cpasync16(sB[buf] + soff, W + (size_t)(n0 + row) * ldb + kc * 64 + q * 8);
        }
        CP_COMMIT();
    };

    issue(0, 0);
    int buf = 0;
    for (int kc = 0; kc < nk; kc++) {
        if (kc + 1 < nk) {
            issue(kc + 1, buf ^ 1);
            CP_WAIT(1);
        } else {
            CP_WAIT(0);
        }
        __syncthreads();
#pragma unroll
        for (int ks = 0; ks < 4; ks++) {
            uint32_t af[4][4], bfr[4][2];
#pragma unroll
            for (int m = 0; m < 4; m++)
                ldsm_x4(af[m], sA[buf] + aOff + (uint32_t)(m * 16 * ROWP + ks * 16) * 2);
#pragma unroll
            for (int n = 0; n < 4; n++)
                ldsm_x2(bfr[n], sB[buf] + bOff + (uint32_t)(n * 8 * ROWP + ks * 16) * 2);
#pragma unroll
            for (int m = 0; m < 4; m++)
#pragma unroll
                for (int n = 0; n < 4; n++)
                    mma16816(acc[m][n], af[m], bfr[n]);
        }
        __syncthreads();
        buf ^= 1;
    }

    // epilogue
    const int rbase = h0 + wm * 64 + (lane >> 2);
    const int cbase = n0 + wn * 32 + 2 * (lane & 3);
#pragma unroll
    for (int m = 0; m < 4; m++) {
#pragma unroll
        for (int n = 0; n < 4; n++) {
            int col = cbase + n * 8;
            float bia0 = bias[col], bia1 = bias[col + 1];
#pragma unroll
            for (int half = 0; half < 2; half++) {
                int row = rbase + m * 16 + half * 8;
                float v0 = acc[m][n][half * 2 + 0] + bia0;
                float v1 = acc[m][n][half * 2 + 1] + bia1;
                if (MODE == 0) {
                    v0 = fmaxf(v0, 0.0f); v1 = fmaxf(v1, 0.0f);
                    *(__nv_bfloat162*)(out_bf + (size_t)row * ldo + col) =
                        __floats2bfloat162_rn(v0, v1);
                } else if (MODE == 1) {
                    size_t g0 = (size_t)col * H_DIM + row;
                    size_t g1 = g0 + H_DIM;
                    v0 += net[g0] + inp[g0];
                    v1 += net[g1] + inp[g1];
                    *(float2*)(xf + (size_t)row * DIMC + col) = make_float2(v0, v1);
                    *(__nv_bfloat162*)(out_bf + (size_t)row * DIMC + col) =
                        __floats2bfloat162_rn(v0, v1);
                } else {
                    float2 px = *(const float2*)(xf + (size_t)row * DIMC + col);
                    v0 += px.x; v1 += px.y;
                    outT[(size_t)col * H_DIM + row] = v0;
                    outT[(size_t)(col + 1) * H_DIM + row] = v1;
                }
            }
        }
    }
}

// ---------------- heads: thread per h, reads transposed out coalescedly ----------------
__global__ void __launch_bounds__(256)
heads_kernel(const float* __restrict__ xt,   // = out, [c][H] layout, c in [0,384)
             const float* __restrict__ dw, const float* __restrict__ db,
             const float* __restrict__ ww, const float* __restrict__ wb,
             float* __restrict__ out) {
    __shared__ float sw[4 * DIMC];
    int tid = threadIdx.x;
    for (int i = tid; i < 2 * DIMC; i += 256) {
        sw[i] = dw[i];
        sw[2 * DIMC + i] = ww[i];
    }
    __syncthreads();
    int h = blockIdx.x * 256 + tid;
    float d0 = 0, d1 = 0, w0 = 0, w1 = 0;
#pragma unroll 4
    for (int c = 0; c < DIMC; c++) {
        float r = fmaxf(xt[(size_t)c * H_DIM + h], 0.0f);
        d0 += r * sw[c];
        d1 += r * sw[DIMC + c];
        w0 += r * sw[2 * DIMC + c];
        w1 += r * sw[3 * DIMC + c];
    }
    size_t base = (size_t)DIMC * H_DIM;
    out[base + 0 * H_DIM + h] = d0 + db[0];
    out[base + 1 * H_DIM + h] = d1 + db[1];
    out[base + 2 * H_DIM + h] = 1.0f / (1.0f + expf(-(w0 + wb[0])));
    out[base + 3 * H_DIM + h] = 1.0f / (1.0f + expf(-(w1 + wb[1])));
}

// ---------------- launch ----------------
extern "C" void kernel_launch(void* const* d_in, const int* in_sizes, int n_in,
                              void* d_out, int out_size) {
    const float* net   = (const float*)d_in[0];
    const float* inp   = (const float*)d_in[1];
    const float* corr  = (const float*)d_in[2];
    const float* cc_w1 = (const float*)d_in[7];
    const float* cc_b1 = (const float*)d_in[8];
    const float* cc_w2 = (const float*)d_in[9];
    const float* cc_b2 = (const float*)d_in[10];
    const float* cc_w3 = (const float*)d_in[11];
    const float* cc_b3 = (const float*)d_in[12];
    const float* c1_w1 = (const float*)d_in[13];
    const float* c1_b1 = (const float*)d_in[14];
    const float* c1_w2 = (const float*)d_in[15];
    const float* c1_b2 = (const float*)d_in[16];
    const float* c2_w1 = (const float*)d_in[17];
    const float* c2_b1 = (const float*)d_in[18];
    const float* c2_w2 = (const float*)d_in[19];
    const float* c2_b2 = (const float*)d_in[20];
    const float* dW    = (const float*)d_in[21];
    const float* dB    = (const float*)d_in[22];
    const float* wW    = (const float*)d_in[23];
    const float* wB    = (const float*)d_in[24];
    float* out = (float*)d_out;

    void *p_cbf, *p_a, *p_b, *p_c, *p_h, *p_xf;
    void *p_w1, *p_w2, *p_w3, *p_w45, *p_w67, *p_b45, *p_b67;
    cudaGetSymbolAddress(&p_cbf, g_cbf);
    cudaGetSymbolAddress(&p_a, g_bufA);
    cudaGetSymbolAddress(&p_b, g_bufB);
    cudaGetSymbolAddress(&p_c, g_bufC);
    cudaGetSymbolAddress(&p_h, g_bufH);
    cudaGetSymbolAddress(&p_xf, g_xf);
    cudaGetSymbolAddress(&p_w1, g_w1);
    cudaGetSymbolAddress(&p_w2, g_w2);
    cudaGetSymbolAddress(&p_w3, g_w3);
    cudaGetSymbolAddress(&p_w45, g_w45);
    cudaGetSymbolAddress(&p_w67, g_w67);
    cudaGetSymbolAddress(&p_b45, g_b45);
    cudaGetSymbolAddress(&p_b67, g_b67);

    cudaFuncSetAttribute(gemm_kernel<0>, cudaFuncAttributeMaxDynamicSharedMemorySize, SMEM_BYTES);
    cudaFuncSetAttribute(gemm_kernel<1>, cudaFuncAttributeMaxDynamicSharedMemorySize, SMEM_BYTES);
    cudaFuncSetAttribute(gemm_kernel<2>, cudaFuncAttributeMaxDynamicSharedMemorySize, SMEM_BYTES);

    typedef __nv_bfloat16 bf;
    // weight/bias prep (one kernel)
    prep_kernel<<<4805, 256>>>(cc_w1, cc_w2, cc_w3,
                               c1_w1, c1_b1, c1_w2, c1_b2,
                               c2_w1, c2_b1, c2_w2, c2_b2,
                               (bf*)p_w1, (bf*)p_w2, (bf*)p_w3, (bf*)p_w45, (bf*)p_w67,
                               (float*)p_b45, (float*)p_b67);
    // corr transpose + convert
    corr_prep_kernel<<<dim3(H_DIM / 128, KPAD / 64), 256>>>(corr, (bf*)p_cbf);

    dim3 g384(3, H_DIM / 128), g768(6, H_DIM / 128);
    // t1 = relu(W1 @ corr + b1)
    gemm_kernel<0><<<g384, 256, SMEM_BYTES>>>((bf*)p_cbf, KPAD, KPAD, (bf*)p_w1, KPAD,
                                              cc_b1, (bf*)p_a, DIMC, nullptr, nullptr, nullptr, nullptr);
    // t2 = relu(W2 @ t1 + b2)
    gemm_kernel<0><<<g384, 256, SMEM_BYTES>>>((bf*)p_a, DIMC, DIMC, (bf*)p_w2, DIMC,
                                              cc_b2, (bf*)p_b, DIMC, nullptr, nullptr, nullptr, nullptr);
    // x4 = (W3 @ t2 + b3) + net + inp  -> xf (fp32) + bufC (bf16)
    gemm_kernel<1><<<g384, 256, SMEM_BYTES>>>((bf*)p_b, DIMC, DIMC, (bf*)p_w3, DIMC,
                                              cc_b3, (bf*)p_c, DIMC, (float*)p_xf, net, inp, nullptr);
    // [h1|h2] = relu(W45 @ x4 + b45)   (N = 768)
    gemm_kernel<0><<<g768, 256, SMEM_BYTES>>>((bf*)p_c, DIMC, DIMC, (bf*)p_w45, DIMC,
                                              (float*)p_b45, (bf*)p_h, 768, nullptr, nullptr, nullptr, nullptr);
    // out[c][h] = xf + W67 @ [h1|h2] + b67   (K = 768, transposed store)
    gemm_kernel<2><<<g384, 256, SMEM_BYTES>>>((bf*)p_h, 768, 768, (bf*)p_w67, 768,
                                              (float*)p_b67, nullptr, 0, (float*)p_xf, nullptr, nullptr, out);
    // heads from transposed out
    heads_kernel<<<H_DIM / 256, 256>>>(out, dW, dB, wW, wB, out);
}